// round 14
// baseline (speedup 1.0000x reference)
#include <cuda_runtime.h>
#include <cuda_fp16.h>
#include <cstdint>

#define NPED 6144
#define HID  256
#define OUTD 32
#define NKC  19        // K chunks of 32: [hi 0..8 | lo 9..17 | emb_hi 18]
#define CROW 40        // halves per row per chunk (32 data + 8 pad) = 80B

// ---------------- scratch (no allocation allowed) ----------------
__device__ float  g_hnew[NPED * HID];
__device__ __align__(16) __half g_X[NKC * NPED * CROW];
__device__ __align__(16) __half g_W[NKC * 1024 * CROW];

// ---------------- helpers ----------------
__device__ __forceinline__ uint32_t smem_u32(const void* p) {
    uint32_t a;
    asm("{ .reg .u64 t; cvta.to.shared.u64 t, %1; cvt.u32.u64 %0, t; }" : "=r"(a) : "l"(p));
    return a;
}
__device__ __forceinline__ void bulk_cp(uint32_t dst, const void* src,
                                        uint32_t bytes, uint32_t mbar) {
    asm volatile("cp.async.bulk.shared::cta.global.mbarrier::complete_tx::bytes "
                 "[%0], [%1], %2, [%3];"
                 :: "r"(dst), "l"(src), "r"(bytes), "r"(mbar) : "memory");
}
#define MBARRIER_INIT(a, c) \
    asm volatile("mbarrier.init.shared.b64 [%0], %1;" :: "r"(a), "r"(c) : "memory")
#define MBARRIER_EXPECT_TX(a, b) \
    asm volatile("mbarrier.arrive.expect_tx.shared.b64 _, [%0], %1;" \
                 :: "r"(a), "r"(b) : "memory")
#define MBAR_WAIT(a, p) do {                                                    \
    uint32_t _m = (a), _p = (p), _d;                                            \
    asm volatile("{\n\t.reg .pred q;\n\t"                                       \
        "mbarrier.try_wait.parity.acquire.cta.shared::cta.b64 q, [%1], %2;\n\t" \
        "selp.b32 %0, 1, 0, q;\n\t}" : "=r"(_d) : "r"(_m), "r"(_p) : "memory"); \
    if (!_d) {                                                                  \
        asm volatile("{\n\t.reg .pred Q;\n\tWL_%=:\n\t"                         \
        "mbarrier.try_wait.parity.acquire.cta.shared::cta.b64 Q, [%0], %1, 0x989680;\n\t" \
        "@Q bra.uni WD_%=;\n\tbra.uni WL_%=;\n\tWD_%=:\n\t}"                    \
        :: "r"(_m), "r"(_p) : "memory");                                        \
    } } while (0)

__device__ __forceinline__ bool dless(float d, int j, float dk, int ik) {
    return (d < dk) | ((d == dk) & (j < ik));
}
__device__ __forceinline__ float sigm(float x) { return 1.f / (1.f + __expf(-x)); }
__device__ __forceinline__ float tanh_f(float x) {
    float xx = fminf(fmaxf(x, -15.f), 15.f);
    float t  = __expf(-2.f * xx);
    return (1.f - t) / (1.f + t);
}
__device__ __forceinline__ ushort2 hilo(float x) {
    __half hb = __float2half_rn(x);
    __half lb = __float2half_rn(x - __half2float(hb));
    ushort2 r; r.x = __half_as_ushort(hb); r.y = __half_as_ushort(lb);
    return r;
}

// branchless lexicographic 4-best insert: pure SEL, no-op when lt3 false.
#define SEL_INSERT(dd, jj)                                                \
    {                                                                     \
        bool lt3 = dless(dd, jj, d3v, i3v);                               \
        bool lt2 = dless(dd, jj, d2v, i2v);                               \
        bool lt1 = dless(dd, jj, d1v, i1v);                               \
        bool lt0 = dless(dd, jj, d0v, i0v);                               \
        float n3 = lt3 ? (lt2 ? d2v : dd) : d3v;                          \
        int   m3 = lt3 ? (lt2 ? i2v : jj) : i3v;                          \
        float n2 = lt2 ? (lt1 ? d1v : dd) : d2v;                          \
        int   m2 = lt2 ? (lt1 ? i1v : jj) : i2v;                          \
        float n1 = lt1 ? (lt0 ? d0v : dd) : d1v;                          \
        int   m1 = lt1 ? (lt0 ? i0v : jj) : i1v;                          \
        float n0 = lt0 ? dd : d0v;                                        \
        int   m0 = lt0 ? jj : i0v;                                        \
        d0v = n0; i0v = m0; d1v = n1; i1v = m1;                           \
        d2v = n2; i2v = m2; d3v = n3; i3v = m3;                           \
    }

// =====================================================================
// Kernel A: 4-NN + embedding. 192 blocks x 256 threads; 8 parts x 768.
// Taken bracket body is straight-line SEL code (single BSSY level).
// =====================================================================
__global__ void __launch_bounds__(256) knn_embed(const float* __restrict__ obs1,
                                                 const float* __restrict__ obs2,
                                                 const float* __restrict__ W_emb,
                                                 const float* __restrict__ b_emb)
{
    extern __shared__ float sm[];
    float2* sPos = (float2*)sm;
    float*  sHn  = sm + 2 * NPED;
    float*  sCd  = sHn + NPED;
    int*    sCi  = (int*)(sCd + 8 * 32 * 4);
    float*  sW   = (float*)(sCi + 8 * 32 * 4);
    ushort* sEh  = (ushort*)(sW + 40);
    ushort* sEl  = sEh + 32 * 32;

    const int tid = threadIdx.x;
    const float2* o2 = (const float2*)obs2;
    const float2* o1 = (const float2*)obs1;
    for (int t = tid; t < NPED; t += 256) {
        float2 p = o2[t];
        sPos[t] = p;
        sHn[t]  = 0.5f * (p.x * p.x + p.y * p.y);
    }
    if (tid < 40) sW[tid] = (tid < 32) ? W_emb[tid] : b_emb[tid - 32];
    __syncthreads();

    const int li = tid & 31, part = tid >> 5;
    const int i = blockIdx.x * 32 + li;
    const float mx = sPos[i].x, my = sPos[i].y;
    const float nmx = -mx, nmy = -my;

    const float INF = __int_as_float(0x7f800000);
    float d0v = INF, d1v = INF, d2v = INF, d3v = INF;
    int   i0v = 0x7fffffff, i1v = 0x7fffffff, i2v = 0x7fffffff, i3v = 0x7fffffff;

    const float4* sP4 = (const float4*)sPos;
    const float4* sH4 = (const float4*)sHn;
    const int gbeg = part * 192, gend = gbeg + 192;
    const int gs = i >> 2;
    const int pSelf = blockIdx.x / 24;

#define GROUP_KEYS()                                                       \
    float4 pa = sP4[g * 2], pb = sP4[g * 2 + 1];                           \
    float4 hn = sH4[g];                                                    \
    float k0 = fmaf(nmx, pa.x, fmaf(nmy, pa.y, hn.x));                     \
    float k1 = fmaf(nmx, pa.z, fmaf(nmy, pa.w, hn.y));                     \
    float k2 = fmaf(nmx, pb.x, fmaf(nmy, pb.y, hn.z));                     \
    float k3 = fmaf(nmx, pb.z, fmaf(nmy, pb.w, hn.w));

#define GROUP_BODY()                                                       \
    float mn = fminf(fminf(k0, k1), fminf(k2, k3));                        \
    if (mn <= d3v) {                                                       \
        int jb = g * 4;                                                    \
        SEL_INSERT(k0, jb + 0);                                            \
        SEL_INSERT(k1, jb + 1);                                            \
        SEL_INSERT(k2, jb + 2);                                            \
        SEL_INSERT(k3, jb + 3);                                            \
    }

    if (part == pSelf) {
        for (int g = gbeg; g < gend; ++g) {
            GROUP_KEYS();
            if (g == gs) {
                int sl = i & 3;
                k0 = (sl == 0) ? INF : k0;
                k1 = (sl == 1) ? INF : k1;
                k2 = (sl == 2) ? INF : k2;
                k3 = (sl == 3) ? INF : k3;
            }
            GROUP_BODY();
        }
    } else {
        for (int g = gbeg; g < gend; ++g) {
            GROUP_KEYS();
            GROUP_BODY();
        }
    }
#undef GROUP_KEYS
#undef GROUP_BODY

    {
        int base = (part * 32 + li) * 4;
        sCd[base + 0] = d0v; sCi[base + 0] = i0v;
        sCd[base + 1] = d1v; sCi[base + 1] = i1v;
        sCd[base + 2] = d2v; sCi[base + 2] = i2v;
        sCd[base + 3] = d3v; sCi[base + 3] = i3v;
    }
    __syncthreads();

    if (part == 0) {
        d0v = d1v = d2v = d3v = INF;
        i0v = i1v = i2v = i3v = 0x7fffffff;
        #pragma unroll
        for (int p = 0; p < 8; ++p)
            #pragma unroll
            for (int s = 0; s < 4; ++s) {
                float dd = sCd[(p * 32 + li) * 4 + s];
                int   jj = sCi[(p * 32 + li) * 4 + s];
                SEL_INSERT(dd, jj);
            }

        float2 o1i = o1[i];
        const float vix = mx - o1i.x, viy = my - o1i.y;
        int nb[4] = {i0v, i1v, i2v, i3v};
        #pragma unroll
        for (int k = 0; k < 4; ++k) {
            float2 np = sPos[nb[k]];
            float2 o1n = o1[nb[k]];
            float px = np.x - mx, py = np.y - my;
            float vx = (np.x - o1n.x) - vix, vy = (np.y - o1n.y) - viy;
            #pragma unroll
            for (int e = 0; e < 8; ++e) {
                float v = sW[32 + e] + px * sW[e] + py * sW[8 + e]
                        + vx * sW[16 + e] + vy * sW[24 + e];
                v = fmaxf(v, 0.f);
                ushort2 hl = hilo(v);
                sEh[li * 32 + k * 8 + e] = hl.x;
                sEl[li * 32 + k * 8 + e] = hl.y;
            }
        }
    }
    __syncthreads();

    // emb -> g_X chunks: hi -> chunk 0, lo -> chunk 9, hi -> chunk 18
    {
        int r = tid >> 3, q = tid & 7;
        int gr = blockIdx.x * 32 + r;
        ushort4 vh = *(const ushort4*)&sEh[r * 32 + q * 4];
        ushort4 vl = *(const ushort4*)&sEl[r * 32 + q * 4];
        *(ushort4*)((ushort*)g_X + ((size_t)(0 * NPED + gr)) * CROW + q * 4)  = vh;
        *(ushort4*)((ushort*)g_X + ((size_t)(9 * NPED + gr)) * CROW + q * 4)  = vl;
        *(ushort4*)((ushort*)g_X + ((size_t)(18 * NPED + gr)) * CROW + q * 4) = vh;
    }
}

// =====================================================================
// prep_x: h [N,256] -> chunks 1..8 (hi) and 10..17 (lo) of g_X
// =====================================================================
__global__ void __launch_bounds__(256) prep_x(const float* __restrict__ h)
{
    int idx = blockIdx.x * 256 + threadIdx.x;     // N * 64
    int row = idx >> 6, q = idx & 63;
    int s = q * 4;
    float4 v = *(const float4*)&h[row * 256 + s];

    ushort2 a = hilo(v.x), b = hilo(v.y), cc = hilo(v.z), d = hilo(v.w);
    ushort4 ph, pl;
    ph.x = a.x; ph.y = b.x; ph.z = cc.x; ph.w = d.x;
    pl.x = a.y; pl.y = b.y; pl.z = cc.y; pl.w = d.y;
    int ch = 1 + (s >> 5), cl = 10 + (s >> 5), ci = s & 31;
    *(ushort4*)((ushort*)g_X + ((size_t)(ch * NPED + row)) * CROW + ci) = ph;
    *(ushort4*)((ushort*)g_X + ((size_t)(cl * NPED + row)) * CROW + ci) = pl;
}

// =====================================================================
// prep_w: W' chunk-major, rows interleaved rowp = j*4+gate.
// =====================================================================
__global__ void __launch_bounds__(256) prep_w(const float* __restrict__ W_ih,
                                              const float* __restrict__ W_hh)
{
    int idx = blockIdx.x * 256 + threadIdx.x;     // 1024 * 76
    int rowp = idx / 76, q = idx - rowp * 76;
    int j = rowp >> 2, gate = rowp & 3;
    int r = gate * 256 + j;

    if (q < 72) {
        int s = q * 4;
        float4 v = (s < 32) ? *(const float4*)&W_ih[r * 32 + s]
                            : *(const float4*)&W_hh[r * 256 + (s - 32)];
        ushort2 a = hilo(v.x), b = hilo(v.y), cc = hilo(v.z), d = hilo(v.w);
        ushort4 ph;
        ph.x = a.x; ph.y = b.x; ph.z = cc.x; ph.w = d.x;
        int c0 = s >> 5, ci = s & 31;
        *(ushort4*)((ushort*)g_W + ((size_t)(c0 * 1024 + rowp)) * CROW + ci)       = ph;
        *(ushort4*)((ushort*)g_W + ((size_t)((c0 + 9) * 1024 + rowp)) * CROW + ci) = ph;
    } else {
        int s2 = (q - 72) * 4;
        float4 v = *(const float4*)&W_ih[r * 32 + s2];
        ushort2 a = hilo(v.x), b = hilo(v.y), cc = hilo(v.z), d = hilo(v.w);
        ushort4 pl;
        pl.x = a.y; pl.y = b.y; pl.z = cc.y; pl.w = d.y;
        *(ushort4*)((ushort*)g_W + ((size_t)(18 * 1024 + rowp)) * CROW + s2) = pl;
    }
}

// ---------------- mma/ldmatrix wrappers ----------------
__device__ __forceinline__ void ldsm_x4(uint32_t* r, uint32_t addr) {
    asm volatile("ldmatrix.sync.aligned.m8n8.x4.shared.b16 {%0,%1,%2,%3}, [%4];"
                 : "=r"(r[0]), "=r"(r[1]), "=r"(r[2]), "=r"(r[3]) : "r"(addr));
}
__device__ __forceinline__ void ldsm_x2(uint32_t* r, uint32_t addr) {
    asm volatile("ldmatrix.sync.aligned.m8n8.x2.shared.b16 {%0,%1}, [%2];"
                 : "=r"(r[0]), "=r"(r[1]) : "r"(addr));
}
__device__ __forceinline__ void mma_f16(float* d, const uint32_t* a, const uint32_t* b) {
    asm volatile("mma.sync.aligned.m16n8k16.row.col.f32.f16.f16.f32 "
                 "{%0,%1,%2,%3}, {%4,%5,%6,%7}, {%8,%9}, {%0,%1,%2,%3};"
                 : "+f"(d[0]), "+f"(d[1]), "+f"(d[2]), "+f"(d[3])
                 : "r"(a[0]), "r"(a[1]), "r"(a[2]), "r"(a[3]), "r"(b[0]), "r"(b[1]));
}

// =====================================================================
// Kernel B: gates GEMM + fused LSTM (R13 config: bulk-copy pipeline).
// =====================================================================
#define SROW     40
#define XBYTES   10240
#define STAGE_SZ 20480
#define NSTAGE   5
#define MBAR_OFF (NSTAGE * STAGE_SZ)

__global__ void __launch_bounds__(256, 2)
gemm_lstm(const float* __restrict__ c,
          const float* __restrict__ b_ih, const float* __restrict__ b_hh)
{
    extern __shared__ char dyn[];
    __shared__ float sbias[128];
    const uint32_t uS = smem_u32(dyn);

    const int tid  = threadIdx.x;
    const int warp = tid >> 5, lane = tid & 31;
    const int n0  = blockIdx.y * 128;
    const int j0w = blockIdx.x * 128;
    const int j0g = blockIdx.x * 32;

    if (tid < 128) {
        int jg = j0g + (tid >> 2), gate = tid & 3;
        sbias[tid] = b_ih[gate * 256 + jg] + b_hh[gate * 256 + jg];
    }
    if (tid < NSTAGE) MBARRIER_INIT(uS + MBAR_OFF + tid * 8, 1);

    const int mw = (warp >> 2) * 64;
    const int nw = (warp & 3) * 32;

    float acc[4][4][4];
    #pragma unroll
    for (int a = 0; a < 4; ++a)
        #pragma unroll
        for (int b = 0; b < 4; ++b)
            #pragma unroll
            for (int r = 0; r < 4; ++r) acc[a][b][r] = 0.f;

    uint32_t aOff[4], bOff[4];
    {
        int arow = mw + ((lane >> 3) & 1) * 8 + (lane & 7);
        int acol = (lane >> 4) * 8;
        #pragma unroll
        for (int mf = 0; mf < 4; ++mf)
            aOff[mf] = ((arow + mf * 16) * SROW + acol) * 2;
        int brow = nw + (lane & 7);
        int bcol = ((lane >> 3) & 1) * 8;
        #pragma unroll
        for (int nf = 0; nf < 4; ++nf)
            bOff[nf] = ((brow + nf * 8) * SROW + bcol) * 2;
    }

    const __half* __restrict__ gX = g_X;
    const __half* __restrict__ gW = g_W;

    auto issue_stage = [&](int s, int kc) {
        uint32_t mb = uS + MBAR_OFF + s * 8;
        uint32_t sb = uS + (uint32_t)s * STAGE_SZ;
        MBARRIER_EXPECT_TX(mb, 2 * XBYTES);
        bulk_cp(sb,          gX + ((size_t)kc * NPED + n0)  * CROW, XBYTES, mb);
        bulk_cp(sb + XBYTES, gW + ((size_t)kc * 1024 + j0w) * CROW, XBYTES, mb);
    };

    __syncthreads();
    if (tid == 0) {
        issue_stage(0, 0);
        issue_stage(1, 1);
        issue_stage(2, 2);
        issue_stage(3, 3);
    }

    for (int kc = 0; kc < NKC; ++kc) {
        if (kc > 0) __syncthreads();
        if (tid == 0 && kc + 4 < NKC)
            issue_stage((kc + 4) % NSTAGE, kc + 4);
        MBAR_WAIT(uS + MBAR_OFF + (kc % NSTAGE) * 8, (uint32_t)((kc / NSTAGE) & 1));

        const uint32_t bufX = uS + (uint32_t)(kc % NSTAGE) * STAGE_SZ;
        const uint32_t bufW = bufX + XBYTES;
        #pragma unroll
        for (int ks = 0; ks < 2; ++ks) {
            uint32_t af[4][4], bf[4][2];
            #pragma unroll
            for (int mf = 0; mf < 4; ++mf)
                ldsm_x4(af[mf], bufX + aOff[mf] + ks * 32);
            #pragma unroll
            for (int nf = 0; nf < 4; ++nf)
                ldsm_x2(bf[nf], bufW + bOff[nf] + ks * 32);
            #pragma unroll
            for (int mf = 0; mf < 4; ++mf)
                #pragma unroll
                for (int nf = 0; nf < 4; ++nf)
                    mma_f16(acc[mf][nf], af[mf], bf[nf]);
        }
    }

    const int tig = lane & 3, g = lane >> 2;
    const bool even = !(tig & 1);
    #pragma unroll
    for (int mf = 0; mf < 4; ++mf) {
        #pragma unroll
        for (int nf = 0; nf < 4; ++nf) {
            float d0 = acc[mf][nf][0], d1 = acc[mf][nf][1];
            float d2 = acc[mf][nf][2], d3 = acc[mf][nf][3];
            float p0 = __shfl_xor_sync(0xffffffffu, d0, 1);
            float p1 = __shfl_xor_sync(0xffffffffu, d1, 1);
            float p2 = __shfl_xor_sync(0xffffffffu, d2, 1);
            float p3 = __shfl_xor_sync(0xffffffffu, d3, 1);
            int cl = nw + nf * 8 + 2 * tig;
            float gi, gf, gg, go;
            int rowl;
            if (even) {
                gi = d0 + sbias[cl];     gf = d1 + sbias[cl + 1];
                gg = p0 + sbias[cl + 2]; go = p1 + sbias[cl + 3];
                rowl = mw + mf * 16 + g;
            } else {
                gi = p2 + sbias[cl - 2]; gf = p3 + sbias[cl - 1];
                gg = d2 + sbias[cl];     go = d3 + sbias[cl + 1];
                rowl = mw + mf * 16 + g + 8;
            }
            int jj = (nw + nf * 8) / 4 + (tig >> 1);
            int n = n0 + rowl, j = j0g + jj;
            float cin = c[n * HID + j];
            float cn  = sigm(gf) * cin + sigm(gi) * tanh_f(gg);
            g_hnew[n * HID + j] = sigm(go) * tanh_f(cn);
        }
    }
}

// =====================================================================
// Kernel C: out = h_new @ W_pool^T + b_pool (R12 config)
// =====================================================================
__global__ void __launch_bounds__(256) out_gemm(const float* __restrict__ W_pool,
                                                const float* __restrict__ b_pool,
                                                float* __restrict__ out)
{
    __shared__ float hs[16][68];
    __shared__ float ws[64][34];
    const int tid = threadIdx.x;
    const int n0 = blockIdx.x * 16;
    const int nl = tid >> 4, og = (tid & 15) * 2;

    float acc0 = 0.f, acc1 = 0.f;

    for (int kc = 0; kc < 4; ++kc) {
        {
            int r = tid >> 4, kq = tid & 15;
            float4 v = *(const float4*)&g_hnew[(n0 + r) * HID + kc * 64 + kq * 4];
            hs[r][kq * 4 + 0] = v.x; hs[r][kq * 4 + 1] = v.y;
            hs[r][kq * 4 + 2] = v.z; hs[r][kq * 4 + 3] = v.w;
        }
        #pragma unroll
        for (int it = 0; it < 2; ++it) {
            int l = tid + 256 * it;
            int o = l >> 4, kq = l & 15;
            float4 v = *(const float4*)&W_pool[o * HID + kc * 64 + kq * 4];
            ws[kq * 4 + 0][o] = v.x; ws[kq * 4 + 1][o] = v.y;
            ws[kq * 4 + 2][o] = v.z; ws[kq * 4 + 3][o] = v.w;
        }
        __syncthreads();
        #pragma unroll
        for (int k = 0; k < 64; k += 4) {
            float4 a = *(const float4*)&hs[nl][k];
            float2 w0 = *(const float2*)&ws[k + 0][og];
            float2 w1 = *(const float2*)&ws[k + 1][og];
            float2 w2 = *(const float2*)&ws[k + 2][og];
            float2 w3 = *(const float2*)&ws[k + 3][og];
            acc0 = fmaf(a.x, w0.x, acc0); acc1 = fmaf(a.x, w0.y, acc1);
            acc0 = fmaf(a.y, w1.x, acc0); acc1 = fmaf(a.y, w1.y, acc1);
            acc0 = fmaf(a.z, w2.x, acc0); acc1 = fmaf(a.z, w2.y, acc1);
            acc0 = fmaf(a.w, w3.x, acc0); acc1 = fmaf(a.w, w3.y, acc1);
        }
        __syncthreads();
    }
    float2 res;
    res.x = acc0 + b_pool[og];
    res.y = acc1 + b_pool[og + 1];
    *(float2*)&out[(n0 + nl) * OUTD + og] = res;
}

// =====================================================================
extern "C" void kernel_launch(void* const* d_in, const int* in_sizes, int n_in,
                              void* d_out, int out_size)
{
    (void)in_sizes; (void)n_in; (void)out_size;
    const float* obs1   = (const float*)d_in[0];
    const float* obs2   = (const float*)d_in[1];
    const float* h      = (const float*)d_in[2];
    const float* c      = (const float*)d_in[3];
    const float* W_emb  = (const float*)d_in[4];
    const float* b_emb  = (const float*)d_in[5];
    const float* W_ih   = (const float*)d_in[6];
    const float* b_ih   = (const float*)d_in[7];
    const float* W_hh   = (const float*)d_in[8];
    const float* b_hh   = (const float*)d_in[9];
    const float* W_pool = (const float*)d_in[10];
    const float* b_pool = (const float*)d_in[11];
    float* out = (float*)d_out;

    size_t smemA = (size_t)(2 * NPED) * 4
                 + (size_t)NPED * 4
                 + (size_t)(8 * 32 * 4) * 4 * 2
                 + 40 * 4
                 + (size_t)(32 * 32) * 2 * 2;
    size_t smemB = (size_t)MBAR_OFF + NSTAGE * 8 + 16;
    cudaFuncSetAttribute(knn_embed, cudaFuncAttributeMaxDynamicSharedMemorySize,
                         (int)smemA);
    cudaFuncSetAttribute(gemm_lstm, cudaFuncAttributeMaxDynamicSharedMemorySize,
                         (int)smemB);

    prep_w   <<<1024 * 76 / 256, 256>>>(W_ih, W_hh);
    prep_x   <<<NPED * 64 / 256, 256>>>(h);
    knn_embed<<<NPED / 32, 256, smemA>>>(obs1, obs2, W_emb, b_emb);
    gemm_lstm<<<dim3(8, 48), 256, smemB>>>(c, b_ih, b_hh);
    out_gemm <<<NPED / 16, 256>>>(W_pool, b_pool, out);
}

// round 15
// speedup vs baseline: 1.1226x; 1.1226x over previous
#include <cuda_runtime.h>
#include <cuda_fp16.h>
#include <cstdint>

#define NPED 6144
#define HID  256
#define OUTD 32
#define NKC  19        // K chunks of 32: [hi 0..8 | lo 9..17 | emb_hi 18]
#define CROW 40        // halves per row per chunk (32 data + 8 pad) = 80B

// ---------------- scratch (no allocation allowed) ----------------
__device__ float  g_hnew[NPED * HID];
__device__ __align__(16) __half g_X[NKC * NPED * CROW];
__device__ __align__(16) __half g_W[NKC * 1024 * CROW];

// ---------------- helpers ----------------
__device__ __forceinline__ uint32_t smem_u32(const void* p) {
    uint32_t a;
    asm("{ .reg .u64 t; cvta.to.shared.u64 t, %1; cvt.u32.u64 %0, t; }" : "=r"(a) : "l"(p));
    return a;
}
__device__ __forceinline__ void bulk_cp(uint32_t dst, const void* src,
                                        uint32_t bytes, uint32_t mbar) {
    asm volatile("cp.async.bulk.shared::cta.global.mbarrier::complete_tx::bytes "
                 "[%0], [%1], %2, [%3];"
                 :: "r"(dst), "l"(src), "r"(bytes), "r"(mbar) : "memory");
}
#define MBARRIER_INIT(a, c) \
    asm volatile("mbarrier.init.shared.b64 [%0], %1;" :: "r"(a), "r"(c) : "memory")
#define MBARRIER_EXPECT_TX(a, b) \
    asm volatile("mbarrier.arrive.expect_tx.shared.b64 _, [%0], %1;" \
                 :: "r"(a), "r"(b) : "memory")
#define MBAR_WAIT(a, p) do {                                                    \
    uint32_t _m = (a), _p = (p), _d;                                            \
    asm volatile("{\n\t.reg .pred q;\n\t"                                       \
        "mbarrier.try_wait.parity.acquire.cta.shared::cta.b64 q, [%1], %2;\n\t" \
        "selp.b32 %0, 1, 0, q;\n\t}" : "=r"(_d) : "r"(_m), "r"(_p) : "memory"); \
    if (!_d) {                                                                  \
        asm volatile("{\n\t.reg .pred Q;\n\tWL_%=:\n\t"                         \
        "mbarrier.try_wait.parity.acquire.cta.shared::cta.b64 Q, [%0], %1, 0x989680;\n\t" \
        "@Q bra.uni WD_%=;\n\tbra.uni WL_%=;\n\tWD_%=:\n\t}"                    \
        :: "r"(_m), "r"(_p) : "memory");                                        \
    } } while (0)

__device__ __forceinline__ bool dless(float d, int j, float dk, int ik) {
    return (d < dk) | ((d == dk) & (j < ik));
}
__device__ __forceinline__ float sigm(float x) { return 1.f / (1.f + __expf(-x)); }
__device__ __forceinline__ float tanh_f(float x) {
    float xx = fminf(fmaxf(x, -15.f), 15.f);
    float t  = __expf(-2.f * xx);
    return (1.f - t) / (1.f + t);
}
__device__ __forceinline__ ushort2 hilo(float x) {
    __half hb = __float2half_rn(x);
    __half lb = __float2half_rn(x - __half2float(hb));
    ushort2 r; r.x = __half_as_ushort(hb); r.y = __half_as_ushort(lb);
    return r;
}

// flattened lexicographic 4-best insert: single branch level, SEL body.
#define FLAT_INSERT(dd, jj)                                               \
    {                                                                     \
        bool lt3 = dless(dd, jj, d3v, i3v);                               \
        if (lt3) {                                                        \
            bool lt2 = dless(dd, jj, d2v, i2v);                           \
            bool lt1 = dless(dd, jj, d1v, i1v);                           \
            bool lt0 = dless(dd, jj, d0v, i0v);                           \
            float n3 = lt2 ? d2v : dd;  int m3 = lt2 ? i2v : jj;          \
            float n2 = lt2 ? (lt1 ? d1v : dd) : d2v;                      \
            int   m2 = lt2 ? (lt1 ? i1v : jj) : i2v;                      \
            float n1 = lt1 ? (lt0 ? d0v : dd) : d1v;                      \
            int   m1 = lt1 ? (lt0 ? i0v : jj) : i1v;                      \
            float n0 = lt0 ? dd : d0v;  int m0 = lt0 ? jj : i0v;          \
            d0v = n0; i0v = m0; d1v = n1; i1v = m1;                       \
            d2v = n2; i2v = m2; d3v = n3; i3v = m3;                       \
        }                                                                 \
    }

// =====================================================================
// Kernel A: 4-NN + embedding (R13 measured-best scan).
// =====================================================================
__global__ void __launch_bounds__(256) knn_embed(const float* __restrict__ obs1,
                                                 const float* __restrict__ obs2,
                                                 const float* __restrict__ W_emb,
                                                 const float* __restrict__ b_emb)
{
    extern __shared__ float sm[];
    float2* sPos = (float2*)sm;
    float*  sHn  = sm + 2 * NPED;
    float*  sCd  = sHn + NPED;
    int*    sCi  = (int*)(sCd + 8 * 32 * 4);
    float*  sW   = (float*)(sCi + 8 * 32 * 4);
    ushort* sEh  = (ushort*)(sW + 40);
    ushort* sEl  = sEh + 32 * 32;

    const int tid = threadIdx.x;
    const float2* o2 = (const float2*)obs2;
    const float2* o1 = (const float2*)obs1;
    for (int t = tid; t < NPED; t += 256) {
        float2 p = o2[t];
        sPos[t] = p;
        sHn[t]  = 0.5f * (p.x * p.x + p.y * p.y);
    }
    if (tid < 40) sW[tid] = (tid < 32) ? W_emb[tid] : b_emb[tid - 32];
    __syncthreads();

    const int li = tid & 31, part = tid >> 5;
    const int i = blockIdx.x * 32 + li;
    const float mx = sPos[i].x, my = sPos[i].y;
    const float nmx = -mx, nmy = -my;

    const float INF = __int_as_float(0x7f800000);
    float d0v = INF, d1v = INF, d2v = INF, d3v = INF;
    int   i0v = 0x7fffffff, i1v = 0x7fffffff, i2v = 0x7fffffff, i3v = 0x7fffffff;

    const float4* sP4 = (const float4*)sPos;
    const float4* sH4 = (const float4*)sHn;
    const int gbeg = part * 192, gend = gbeg + 192;
    const int gs = i >> 2;
    const int pSelf = blockIdx.x / 24;

#define GROUP_KEYS()                                                       \
    float4 pa = sP4[g * 2], pb = sP4[g * 2 + 1];                           \
    float4 hn = sH4[g];                                                    \
    float k0 = fmaf(nmx, pa.x, fmaf(nmy, pa.y, hn.x));                     \
    float k1 = fmaf(nmx, pa.z, fmaf(nmy, pa.w, hn.y));                     \
    float k2 = fmaf(nmx, pb.x, fmaf(nmy, pb.y, hn.z));                     \
    float k3 = fmaf(nmx, pb.z, fmaf(nmy, pb.w, hn.w));

#define GROUP_BODY()                                                       \
    float mn = fminf(fminf(k0, k1), fminf(k2, k3));                        \
    if (mn <= d3v) {                                                       \
        int jb = g * 4;                                                    \
        if (k0 <= d3v) { FLAT_INSERT(k0, jb + 0); }                        \
        if (k1 <= d3v) { FLAT_INSERT(k1, jb + 1); }                        \
        if (k2 <= d3v) { FLAT_INSERT(k2, jb + 2); }                        \
        if (k3 <= d3v) { FLAT_INSERT(k3, jb + 3); }                        \
    }

    if (part == pSelf) {
        for (int g = gbeg; g < gend; ++g) {
            GROUP_KEYS();
            if (g == gs) {
                int sl = i & 3;
                k0 = (sl == 0) ? INF : k0;
                k1 = (sl == 1) ? INF : k1;
                k2 = (sl == 2) ? INF : k2;
                k3 = (sl == 3) ? INF : k3;
            }
            GROUP_BODY();
        }
    } else {
        for (int g = gbeg; g < gend; ++g) {
            GROUP_KEYS();
            GROUP_BODY();
        }
    }
#undef GROUP_KEYS
#undef GROUP_BODY

    {
        int base = (part * 32 + li) * 4;
        sCd[base + 0] = d0v; sCi[base + 0] = i0v;
        sCd[base + 1] = d1v; sCi[base + 1] = i1v;
        sCd[base + 2] = d2v; sCi[base + 2] = i2v;
        sCd[base + 3] = d3v; sCi[base + 3] = i3v;
    }
    __syncthreads();

    if (part == 0) {
        d0v = d1v = d2v = d3v = INF;
        i0v = i1v = i2v = i3v = 0x7fffffff;
        #pragma unroll
        for (int p = 0; p < 8; ++p)
            #pragma unroll
            for (int s = 0; s < 4; ++s) {
                float dd = sCd[(p * 32 + li) * 4 + s];
                int   jj = sCi[(p * 32 + li) * 4 + s];
                FLAT_INSERT(dd, jj);
            }

        float2 o1i = o1[i];
        const float vix = mx - o1i.x, viy = my - o1i.y;
        int nb[4] = {i0v, i1v, i2v, i3v};
        #pragma unroll
        for (int k = 0; k < 4; ++k) {
            float2 np = sPos[nb[k]];
            float2 o1n = o1[nb[k]];
            float px = np.x - mx, py = np.y - my;
            float vx = (np.x - o1n.x) - vix, vy = (np.y - o1n.y) - viy;
            #pragma unroll
            for (int e = 0; e < 8; ++e) {
                float v = sW[32 + e] + px * sW[e] + py * sW[8 + e]
                        + vx * sW[16 + e] + vy * sW[24 + e];
                v = fmaxf(v, 0.f);
                ushort2 hl = hilo(v);
                sEh[li * 32 + k * 8 + e] = hl.x;
                sEl[li * 32 + k * 8 + e] = hl.y;
            }
        }
    }
    __syncthreads();

    // emb -> g_X chunks: hi -> chunk 0, lo -> chunk 9, hi -> chunk 18
    {
        int r = tid >> 3, q = tid & 7;
        int gr = blockIdx.x * 32 + r;
        ushort4 vh = *(const ushort4*)&sEh[r * 32 + q * 4];
        ushort4 vl = *(const ushort4*)&sEl[r * 32 + q * 4];
        *(ushort4*)((ushort*)g_X + ((size_t)(0 * NPED + gr)) * CROW + q * 4)  = vh;
        *(ushort4*)((ushort*)g_X + ((size_t)(9 * NPED + gr)) * CROW + q * 4)  = vl;
        *(ushort4*)((ushort*)g_X + ((size_t)(18 * NPED + gr)) * CROW + q * 4) = vh;
    }
}

// =====================================================================
// prep_xw: fused prep_x + prep_w (one launch).
// Indices [0, NPED*64)                -> h rows (chunks 1..8 hi, 10..17 lo)
// Indices [NPED*64, NPED*64 + 1024*76) -> W rows (chunk-major)
// =====================================================================
#define PX_TOT (NPED * 64)
#define PW_TOT (1024 * 76)
__global__ void __launch_bounds__(256) prep_xw(const float* __restrict__ h,
                                               const float* __restrict__ W_ih,
                                               const float* __restrict__ W_hh)
{
    int idx = blockIdx.x * 256 + threadIdx.x;
    if (idx < PX_TOT) {
        int row = idx >> 6, q = idx & 63;
        int s = q * 4;
        float4 v = *(const float4*)&h[row * 256 + s];
        ushort2 a = hilo(v.x), b = hilo(v.y), cc = hilo(v.z), d = hilo(v.w);
        ushort4 ph, pl;
        ph.x = a.x; ph.y = b.x; ph.z = cc.x; ph.w = d.x;
        pl.x = a.y; pl.y = b.y; pl.z = cc.y; pl.w = d.y;
        int ch = 1 + (s >> 5), cl = 10 + (s >> 5), ci = s & 31;
        *(ushort4*)((ushort*)g_X + ((size_t)(ch * NPED + row)) * CROW + ci) = ph;
        *(ushort4*)((ushort*)g_X + ((size_t)(cl * NPED + row)) * CROW + ci) = pl;
    } else if (idx < PX_TOT + PW_TOT) {
        int widx = idx - PX_TOT;
        int rowp = widx / 76, q = widx - rowp * 76;
        int j = rowp >> 2, gate = widx & 0;   // placeholder (recomputed below)
        gate = rowp & 3;
        int r = gate * 256 + j;
        if (q < 72) {
            int s = q * 4;
            float4 v = (s < 32) ? *(const float4*)&W_ih[r * 32 + s]
                                : *(const float4*)&W_hh[r * 256 + (s - 32)];
            ushort2 a = hilo(v.x), b = hilo(v.y), cc = hilo(v.z), d = hilo(v.w);
            ushort4 ph;
            ph.x = a.x; ph.y = b.x; ph.z = cc.x; ph.w = d.x;
            int c0 = s >> 5, ci = s & 31;
            *(ushort4*)((ushort*)g_W + ((size_t)(c0 * 1024 + rowp)) * CROW + ci)       = ph;
            *(ushort4*)((ushort*)g_W + ((size_t)((c0 + 9) * 1024 + rowp)) * CROW + ci) = ph;
        } else {
            int s2 = (q - 72) * 4;
            float4 v = *(const float4*)&W_ih[r * 32 + s2];
            ushort2 a = hilo(v.x), b = hilo(v.y), cc = hilo(v.z), d = hilo(v.w);
            ushort4 pl;
            pl.x = a.y; pl.y = b.y; pl.z = cc.y; pl.w = d.y;
            *(ushort4*)((ushort*)g_W + ((size_t)(18 * 1024 + rowp)) * CROW + s2) = pl;
        }
    }
}

// ---------------- mma/ldmatrix wrappers ----------------
__device__ __forceinline__ void ldsm_x4(uint32_t* r, uint32_t addr) {
    asm volatile("ldmatrix.sync.aligned.m8n8.x4.shared.b16 {%0,%1,%2,%3}, [%4];"
                 : "=r"(r[0]), "=r"(r[1]), "=r"(r[2]), "=r"(r[3]) : "r"(addr));
}
__device__ __forceinline__ void ldsm_x2(uint32_t* r, uint32_t addr) {
    asm volatile("ldmatrix.sync.aligned.m8n8.x2.shared.b16 {%0,%1}, [%2];"
                 : "=r"(r[0]), "=r"(r[1]) : "r"(addr));
}
__device__ __forceinline__ void mma_f16(float* d, const uint32_t* a, const uint32_t* b) {
    asm volatile("mma.sync.aligned.m16n8k16.row.col.f32.f16.f16.f32 "
                 "{%0,%1,%2,%3}, {%4,%5,%6,%7}, {%8,%9}, {%0,%1,%2,%3};"
                 : "+f"(d[0]), "+f"(d[1]), "+f"(d[2]), "+f"(d[3])
                 : "r"(a[0]), "r"(a[1]), "r"(a[2]), "r"(a[3]), "r"(b[0]), "r"(b[1]));
}

// =====================================================================
// Kernel B: gates GEMM + fused LSTM (R13/R14 bulk-copy pipeline).
// =====================================================================
#define SROW     40
#define XBYTES   10240
#define STAGE_SZ 20480
#define NSTAGE   5
#define MBAR_OFF (NSTAGE * STAGE_SZ)

__global__ void __launch_bounds__(256, 2)
gemm_lstm(const float* __restrict__ c,
          const float* __restrict__ b_ih, const float* __restrict__ b_hh)
{
    extern __shared__ char dyn[];
    __shared__ float sbias[128];
    const uint32_t uS = smem_u32(dyn);

    const int tid  = threadIdx.x;
    const int warp = tid >> 5, lane = tid & 31;
    const int n0  = blockIdx.y * 128;
    const int j0w = blockIdx.x * 128;
    const int j0g = blockIdx.x * 32;

    if (tid < 128) {
        int jg = j0g + (tid >> 2), gate = tid & 3;
        sbias[tid] = b_ih[gate * 256 + jg] + b_hh[gate * 256 + jg];
    }
    if (tid < NSTAGE) MBARRIER_INIT(uS + MBAR_OFF + tid * 8, 1);

    const int mw = (warp >> 2) * 64;
    const int nw = (warp & 3) * 32;

    float acc[4][4][4];
    #pragma unroll
    for (int a = 0; a < 4; ++a)
        #pragma unroll
        for (int b = 0; b < 4; ++b)
            #pragma unroll
            for (int r = 0; r < 4; ++r) acc[a][b][r] = 0.f;

    uint32_t aOff[4], bOff[4];
    {
        int arow = mw + ((lane >> 3) & 1) * 8 + (lane & 7);
        int acol = (lane >> 4) * 8;
        #pragma unroll
        for (int mf = 0; mf < 4; ++mf)
            aOff[mf] = ((arow + mf * 16) * SROW + acol) * 2;
        int brow = nw + (lane & 7);
        int bcol = ((lane >> 3) & 1) * 8;
        #pragma unroll
        for (int nf = 0; nf < 4; ++nf)
            bOff[nf] = ((brow + nf * 8) * SROW + bcol) * 2;
    }

    const __half* __restrict__ gX = g_X;
    const __half* __restrict__ gW = g_W;

    auto issue_stage = [&](int s, int kc) {
        uint32_t mb = uS + MBAR_OFF + s * 8;
        uint32_t sb = uS + (uint32_t)s * STAGE_SZ;
        MBARRIER_EXPECT_TX(mb, 2 * XBYTES);
        bulk_cp(sb,          gX + ((size_t)kc * NPED + n0)  * CROW, XBYTES, mb);
        bulk_cp(sb + XBYTES, gW + ((size_t)kc * 1024 + j0w) * CROW, XBYTES, mb);
    };

    __syncthreads();
    if (tid == 0) {
        issue_stage(0, 0);
        issue_stage(1, 1);
        issue_stage(2, 2);
        issue_stage(3, 3);
    }

    for (int kc = 0; kc < NKC; ++kc) {
        if (kc > 0) __syncthreads();
        if (tid == 0 && kc + 4 < NKC)
            issue_stage((kc + 4) % NSTAGE, kc + 4);
        MBAR_WAIT(uS + MBAR_OFF + (kc % NSTAGE) * 8, (uint32_t)((kc / NSTAGE) & 1));

        const uint32_t bufX = uS + (uint32_t)(kc % NSTAGE) * STAGE_SZ;
        const uint32_t bufW = bufX + XBYTES;
        #pragma unroll
        for (int ks = 0; ks < 2; ++ks) {
            uint32_t af[4][4], bf[4][2];
            #pragma unroll
            for (int mf = 0; mf < 4; ++mf)
                ldsm_x4(af[mf], bufX + aOff[mf] + ks * 32);
            #pragma unroll
            for (int nf = 0; nf < 4; ++nf)
                ldsm_x2(bf[nf], bufW + bOff[nf] + ks * 32);
            #pragma unroll
            for (int mf = 0; mf < 4; ++mf)
                #pragma unroll
                for (int nf = 0; nf < 4; ++nf)
                    mma_f16(acc[mf][nf], af[mf], bf[nf]);
        }
    }

    const int tig = lane & 3, g = lane >> 2;
    const bool even = !(tig & 1);
    #pragma unroll
    for (int mf = 0; mf < 4; ++mf) {
        #pragma unroll
        for (int nf = 0; nf < 4; ++nf) {
            float d0 = acc[mf][nf][0], d1 = acc[mf][nf][1];
            float d2 = acc[mf][nf][2], d3 = acc[mf][nf][3];
            float p0 = __shfl_xor_sync(0xffffffffu, d0, 1);
            float p1 = __shfl_xor_sync(0xffffffffu, d1, 1);
            float p2 = __shfl_xor_sync(0xffffffffu, d2, 1);
            float p3 = __shfl_xor_sync(0xffffffffu, d3, 1);
            int cl = nw + nf * 8 + 2 * tig;
            float gi, gf, gg, go;
            int rowl;
            if (even) {
                gi = d0 + sbias[cl];     gf = d1 + sbias[cl + 1];
                gg = p0 + sbias[cl + 2]; go = p1 + sbias[cl + 3];
                rowl = mw + mf * 16 + g;
            } else {
                gi = p2 + sbias[cl - 2]; gf = p3 + sbias[cl - 1];
                gg = d2 + sbias[cl];     go = d3 + sbias[cl + 1];
                rowl = mw + mf * 16 + g + 8;
            }
            int jj = (nw + nf * 8) / 4 + (tig >> 1);
            int n = n0 + rowl, j = j0g + jj;
            float cin = c[n * HID + j];
            float cn  = sigm(gf) * cin + sigm(gi) * tanh_f(gg);
            g_hnew[n * HID + j] = sigm(go) * tanh_f(cn);
        }
    }
}

// =====================================================================
// Kernel C: out = h_new @ W_pool^T + b_pool (R12 config)
// =====================================================================
__global__ void __launch_bounds__(256) out_gemm(const float* __restrict__ W_pool,
                                                const float* __restrict__ b_pool,
                                                float* __restrict__ out)
{
    __shared__ float hs[16][68];
    __shared__ float ws[64][34];
    const int tid = threadIdx.x;
    const int n0 = blockIdx.x * 16;
    const int nl = tid >> 4, og = (tid & 15) * 2;

    float acc0 = 0.f, acc1 = 0.f;

    for (int kc = 0; kc < 4; ++kc) {
        {
            int r = tid >> 4, kq = tid & 15;
            float4 v = *(const float4*)&g_hnew[(n0 + r) * HID + kc * 64 + kq * 4];
            hs[r][kq * 4 + 0] = v.x; hs[r][kq * 4 + 1] = v.y;
            hs[r][kq * 4 + 2] = v.z; hs[r][kq * 4 + 3] = v.w;
        }
        #pragma unroll
        for (int it = 0; it < 2; ++it) {
            int l = tid + 256 * it;
            int o = l >> 4, kq = l & 15;
            float4 v = *(const float4*)&W_pool[o * HID + kc * 64 + kq * 4];
            ws[kq * 4 + 0][o] = v.x; ws[kq * 4 + 1][o] = v.y;
            ws[kq * 4 + 2][o] = v.z; ws[kq * 4 + 3][o] = v.w;
        }
        __syncthreads();
        #pragma unroll
        for (int k = 0; k < 64; k += 4) {
            float4 a = *(const float4*)&hs[nl][k];
            float2 w0 = *(const float2*)&ws[k + 0][og];
            float2 w1 = *(const float2*)&ws[k + 1][og];
            float2 w2 = *(const float2*)&ws[k + 2][og];
            float2 w3 = *(const float2*)&ws[k + 3][og];
            acc0 = fmaf(a.x, w0.x, acc0); acc1 = fmaf(a.x, w0.y, acc1);
            acc0 = fmaf(a.y, w1.x, acc0); acc1 = fmaf(a.y, w1.y, acc1);
            acc0 = fmaf(a.z, w2.x, acc0); acc1 = fmaf(a.z, w2.y, acc1);
            acc0 = fmaf(a.w, w3.x, acc0); acc1 = fmaf(a.w, w3.y, acc1);
        }
        __syncthreads();
    }
    float2 res;
    res.x = acc0 + b_pool[og];
    res.y = acc1 + b_pool[og + 1];
    *(float2*)&out[(n0 + nl) * OUTD + og] = res;
}

// =====================================================================
extern "C" void kernel_launch(void* const* d_in, const int* in_sizes, int n_in,
                              void* d_out, int out_size)
{
    (void)in_sizes; (void)n_in; (void)out_size;
    const float* obs1   = (const float*)d_in[0];
    const float* obs2   = (const float*)d_in[1];
    const float* h      = (const float*)d_in[2];
    const float* c      = (const float*)d_in[3];
    const float* W_emb  = (const float*)d_in[4];
    const float* b_emb  = (const float*)d_in[5];
    const float* W_ih   = (const float*)d_in[6];
    const float* b_ih   = (const float*)d_in[7];
    const float* W_hh   = (const float*)d_in[8];
    const float* b_hh   = (const float*)d_in[9];
    const float* W_pool = (const float*)d_in[10];
    const float* b_pool = (const float*)d_in[11];
    float* out = (float*)d_out;

    size_t smemA = (size_t)(2 * NPED) * 4
                 + (size_t)NPED * 4
                 + (size_t)(8 * 32 * 4) * 4 * 2
                 + 40 * 4
                 + (size_t)(32 * 32) * 2 * 2;
    size_t smemB = (size_t)MBAR_OFF + NSTAGE * 8 + 16;
    cudaFuncSetAttribute(knn_embed, cudaFuncAttributeMaxDynamicSharedMemorySize,
                         (int)smemA);
    cudaFuncSetAttribute(gemm_lstm, cudaFuncAttributeMaxDynamicSharedMemorySize,
                         (int)smemB);

    prep_xw  <<<(PX_TOT + PW_TOT + 255) / 256, 256>>>(h, W_ih, W_hh);
    knn_embed<<<NPED / 32, 256, smemA>>>(obs1, obs2, W_emb, b_emb);
    gemm_lstm<<<dim3(8, 48), 256, smemB>>>(c, b_ih, b_hh);
    out_gemm <<<NPED / 16, 256>>>(W_pool, b_pool, out);
}

// round 16
// speedup vs baseline: 1.2225x; 1.0889x over previous
#include <cuda_runtime.h>
#include <cuda_fp16.h>
#include <cstdint>

#define NPED 6144
#define HID  256
#define OUTD 32
#define NKC  11        // chunks: [hi 0..8 | emb_lo*Wih_hi 9 | emb_hi*Wih_lo 10]
#define CROW 40        // halves per row per chunk (32 data + 8 pad) = 80B

// ---------------- scratch (no allocation allowed) ----------------
__device__ float  g_hnew[NPED * HID];
__device__ __align__(16) __half g_X[NKC * NPED * CROW];
__device__ __align__(16) __half g_W[NKC * 1024 * CROW];

// ---------------- helpers ----------------
__device__ __forceinline__ uint32_t smem_u32(const void* p) {
    uint32_t a;
    asm("{ .reg .u64 t; cvta.to.shared.u64 t, %1; cvt.u32.u64 %0, t; }" : "=r"(a) : "l"(p));
    return a;
}
__device__ __forceinline__ void bulk_cp(uint32_t dst, const void* src,
                                        uint32_t bytes, uint32_t mbar) {
    asm volatile("cp.async.bulk.shared::cta.global.mbarrier::complete_tx::bytes "
                 "[%0], [%1], %2, [%3];"
                 :: "r"(dst), "l"(src), "r"(bytes), "r"(mbar) : "memory");
}
#define MBARRIER_INIT(a, c) \
    asm volatile("mbarrier.init.shared.b64 [%0], %1;" :: "r"(a), "r"(c) : "memory")
#define MBARRIER_EXPECT_TX(a, b) \
    asm volatile("mbarrier.arrive.expect_tx.shared.b64 _, [%0], %1;" \
                 :: "r"(a), "r"(b) : "memory")
#define MBAR_WAIT(a, p) do {                                                    \
    uint32_t _m = (a), _p = (p), _d;                                            \
    asm volatile("{\n\t.reg .pred q;\n\t"                                       \
        "mbarrier.try_wait.parity.acquire.cta.shared::cta.b64 q, [%1], %2;\n\t" \
        "selp.b32 %0, 1, 0, q;\n\t}" : "=r"(_d) : "r"(_m), "r"(_p) : "memory"); \
    if (!_d) {                                                                  \
        asm volatile("{\n\t.reg .pred Q;\n\tWL_%=:\n\t"                         \
        "mbarrier.try_wait.parity.acquire.cta.shared::cta.b64 Q, [%0], %1, 0x989680;\n\t" \
        "@Q bra.uni WD_%=;\n\tbra.uni WL_%=;\n\tWD_%=:\n\t}"                    \
        :: "r"(_m), "r"(_p) : "memory");                                        \
    } } while (0)

__device__ __forceinline__ bool dless(float d, int j, float dk, int ik) {
    return (d < dk) | ((d == dk) & (j < ik));
}
__device__ __forceinline__ float sigm(float x) { return 1.f / (1.f + __expf(-x)); }
__device__ __forceinline__ float tanh_f(float x) {
    float xx = fminf(fmaxf(x, -15.f), 15.f);
    float t  = __expf(-2.f * xx);
    return (1.f - t) / (1.f + t);
}
__device__ __forceinline__ ushort2 hilo(float x) {
    __half hb = __float2half_rn(x);
    __half lb = __float2half_rn(x - __half2float(hb));
    ushort2 r; r.x = __half_as_ushort(hb); r.y = __half_as_ushort(lb);
    return r;
}

// flattened lexicographic 4-best insert: single branch level, SEL body.
#define FLAT_INSERT(dd, jj)                                               \
    {                                                                     \
        bool lt3 = dless(dd, jj, d3v, i3v);                               \
        if (lt3) {                                                        \
            bool lt2 = dless(dd, jj, d2v, i2v);                           \
            bool lt1 = dless(dd, jj, d1v, i1v);                           \
            bool lt0 = dless(dd, jj, d0v, i0v);                           \
            float n3 = lt2 ? d2v : dd;  int m3 = lt2 ? i2v : jj;          \
            float n2 = lt2 ? (lt1 ? d1v : dd) : d2v;                      \
            int   m2 = lt2 ? (lt1 ? i1v : jj) : i2v;                      \
            float n1 = lt1 ? (lt0 ? d0v : dd) : d1v;                      \
            int   m1 = lt1 ? (lt0 ? i0v : jj) : i1v;                      \
            float n0 = lt0 ? dd : d0v;  int m0 = lt0 ? jj : i0v;          \
            d0v = n0; i0v = m0; d1v = n1; i1v = m1;                       \
            d2v = n2; i2v = m2; d3v = n3; i3v = m3;                       \
        }                                                                 \
    }

// =====================================================================
// Kernel A: 4-NN + embedding (R13/R15 measured-best scan).
// =====================================================================
__global__ void __launch_bounds__(256) knn_embed(const float* __restrict__ obs1,
                                                 const float* __restrict__ obs2,
                                                 const float* __restrict__ W_emb,
                                                 const float* __restrict__ b_emb)
{
    extern __shared__ float sm[];
    float2* sPos = (float2*)sm;
    float*  sHn  = sm + 2 * NPED;
    float*  sCd  = sHn + NPED;
    int*    sCi  = (int*)(sCd + 8 * 32 * 4);
    float*  sW   = (float*)(sCi + 8 * 32 * 4);
    ushort* sEh  = (ushort*)(sW + 40);
    ushort* sEl  = sEh + 32 * 32;

    const int tid = threadIdx.x;
    const float2* o2 = (const float2*)obs2;
    const float2* o1 = (const float2*)obs1;
    for (int t = tid; t < NPED; t += 256) {
        float2 p = o2[t];
        sPos[t] = p;
        sHn[t]  = 0.5f * (p.x * p.x + p.y * p.y);
    }
    if (tid < 40) sW[tid] = (tid < 32) ? W_emb[tid] : b_emb[tid - 32];
    __syncthreads();

    const int li = tid & 31, part = tid >> 5;
    const int i = blockIdx.x * 32 + li;
    const float mx = sPos[i].x, my = sPos[i].y;
    const float nmx = -mx, nmy = -my;

    const float INF = __int_as_float(0x7f800000);
    float d0v = INF, d1v = INF, d2v = INF, d3v = INF;
    int   i0v = 0x7fffffff, i1v = 0x7fffffff, i2v = 0x7fffffff, i3v = 0x7fffffff;

    const float4* sP4 = (const float4*)sPos;
    const float4* sH4 = (const float4*)sHn;
    const int gbeg = part * 192, gend = gbeg + 192;
    const int gs = i >> 2;
    const int pSelf = blockIdx.x / 24;

#define GROUP_KEYS()                                                       \
    float4 pa = sP4[g * 2], pb = sP4[g * 2 + 1];                           \
    float4 hn = sH4[g];                                                    \
    float k0 = fmaf(nmx, pa.x, fmaf(nmy, pa.y, hn.x));                     \
    float k1 = fmaf(nmx, pa.z, fmaf(nmy, pa.w, hn.y));                     \
    float k2 = fmaf(nmx, pb.x, fmaf(nmy, pb.y, hn.z));                     \
    float k3 = fmaf(nmx, pb.z, fmaf(nmy, pb.w, hn.w));

#define GROUP_BODY()                                                       \
    float mn = fminf(fminf(k0, k1), fminf(k2, k3));                        \
    if (mn <= d3v) {                                                       \
        int jb = g * 4;                                                    \
        if (k0 <= d3v) { FLAT_INSERT(k0, jb + 0); }                        \
        if (k1 <= d3v) { FLAT_INSERT(k1, jb + 1); }                        \
        if (k2 <= d3v) { FLAT_INSERT(k2, jb + 2); }                        \
        if (k3 <= d3v) { FLAT_INSERT(k3, jb + 3); }                        \
    }

    if (part == pSelf) {
        for (int g = gbeg; g < gend; ++g) {
            GROUP_KEYS();
            if (g == gs) {
                int sl = i & 3;
                k0 = (sl == 0) ? INF : k0;
                k1 = (sl == 1) ? INF : k1;
                k2 = (sl == 2) ? INF : k2;
                k3 = (sl == 3) ? INF : k3;
            }
            GROUP_BODY();
        }
    } else {
        for (int g = gbeg; g < gend; ++g) {
            GROUP_KEYS();
            GROUP_BODY();
        }
    }
#undef GROUP_KEYS
#undef GROUP_BODY

    {
        int base = (part * 32 + li) * 4;
        sCd[base + 0] = d0v; sCi[base + 0] = i0v;
        sCd[base + 1] = d1v; sCi[base + 1] = i1v;
        sCd[base + 2] = d2v; sCi[base + 2] = i2v;
        sCd[base + 3] = d3v; sCi[base + 3] = i3v;
    }
    __syncthreads();

    if (part == 0) {
        d0v = d1v = d2v = d3v = INF;
        i0v = i1v = i2v = i3v = 0x7fffffff;
        #pragma unroll
        for (int p = 0; p < 8; ++p)
            #pragma unroll
            for (int s = 0; s < 4; ++s) {
                float dd = sCd[(p * 32 + li) * 4 + s];
                int   jj = sCi[(p * 32 + li) * 4 + s];
                FLAT_INSERT(dd, jj);
            }

        float2 o1i = o1[i];
        const float vix = mx - o1i.x, viy = my - o1i.y;
        int nb[4] = {i0v, i1v, i2v, i3v};
        #pragma unroll
        for (int k = 0; k < 4; ++k) {
            float2 np = sPos[nb[k]];
            float2 o1n = o1[nb[k]];
            float px = np.x - mx, py = np.y - my;
            float vx = (np.x - o1n.x) - vix, vy = (np.y - o1n.y) - viy;
            #pragma unroll
            for (int e = 0; e < 8; ++e) {
                float v = sW[32 + e] + px * sW[e] + py * sW[8 + e]
                        + vx * sW[16 + e] + vy * sW[24 + e];
                v = fmaxf(v, 0.f);
                ushort2 hl = hilo(v);
                sEh[li * 32 + k * 8 + e] = hl.x;
                sEl[li * 32 + k * 8 + e] = hl.y;
            }
        }
    }
    __syncthreads();

    // emb -> g_X chunks: hi -> chunk 0, lo -> chunk 9, hi -> chunk 10
    {
        int r = tid >> 3, q = tid & 7;
        int gr = blockIdx.x * 32 + r;
        ushort4 vh = *(const ushort4*)&sEh[r * 32 + q * 4];
        ushort4 vl = *(const ushort4*)&sEl[r * 32 + q * 4];
        *(ushort4*)((ushort*)g_X + ((size_t)(0 * NPED + gr)) * CROW + q * 4)  = vh;
        *(ushort4*)((ushort*)g_X + ((size_t)(9 * NPED + gr)) * CROW + q * 4)  = vl;
        *(ushort4*)((ushort*)g_X + ((size_t)(10 * NPED + gr)) * CROW + q * 4) = vh;
    }
}

// =====================================================================
// prep_xw: fused prep_x + prep_w (one launch).
// X part: h rows -> chunks 1..8 (hi only; h_lo correction dropped).
// W part: chunks 0..8 = [Wih_hi|Whh_hi]; 9 = Wih_hi; 10 = Wih_lo.
// =====================================================================
#define PX_TOT (NPED * 64)
#define PW_TOT (1024 * 76)
__global__ void __launch_bounds__(256) prep_xw(const float* __restrict__ h,
                                               const float* __restrict__ W_ih,
                                               const float* __restrict__ W_hh)
{
    int idx = blockIdx.x * 256 + threadIdx.x;
    if (idx < PX_TOT) {
        int row = idx >> 6, q = idx & 63;
        int s = q * 4;
        float4 v = *(const float4*)&h[row * 256 + s];
        __half h0 = __float2half_rn(v.x), h1 = __float2half_rn(v.y);
        __half h2 = __float2half_rn(v.z), h3 = __float2half_rn(v.w);
        ushort4 ph;
        ph.x = __half_as_ushort(h0); ph.y = __half_as_ushort(h1);
        ph.z = __half_as_ushort(h2); ph.w = __half_as_ushort(h3);
        int ch = 1 + (s >> 5), ci = s & 31;
        *(ushort4*)((ushort*)g_X + ((size_t)(ch * NPED + row)) * CROW + ci) = ph;
    } else if (idx < PX_TOT + PW_TOT) {
        int widx = idx - PX_TOT;
        int rowp = widx / 76, q = widx - rowp * 76;
        int j = rowp >> 2, gate = rowp & 3;
        int r = gate * 256 + j;
        if (q < 72) {
            int s = q * 4;
            float4 v = (s < 32) ? *(const float4*)&W_ih[r * 32 + s]
                                : *(const float4*)&W_hh[r * 256 + (s - 32)];
            ushort2 a = hilo(v.x), b = hilo(v.y), cc = hilo(v.z), d = hilo(v.w);
            ushort4 ph;
            ph.x = a.x; ph.y = b.x; ph.z = cc.x; ph.w = d.x;
            int c0 = s >> 5, ci = s & 31;
            *(ushort4*)((ushort*)g_W + ((size_t)(c0 * 1024 + rowp)) * CROW + ci) = ph;
            if (c0 == 0)   // chunk 9 multiplies emb_lo with the same Wih_hi
                *(ushort4*)((ushort*)g_W + ((size_t)(9 * 1024 + rowp)) * CROW + ci) = ph;
        } else {
            int s2 = (q - 72) * 4;
            float4 v = *(const float4*)&W_ih[r * 32 + s2];
            ushort2 a = hilo(v.x), b = hilo(v.y), cc = hilo(v.z), d = hilo(v.w);
            ushort4 pl;
            pl.x = a.y; pl.y = b.y; pl.z = cc.y; pl.w = d.y;
            *(ushort4*)((ushort*)g_W + ((size_t)(10 * 1024 + rowp)) * CROW + s2) = pl;
        }
    }
}

// ---------------- mma/ldmatrix wrappers ----------------
__device__ __forceinline__ void ldsm_x4(uint32_t* r, uint32_t addr) {
    asm volatile("ldmatrix.sync.aligned.m8n8.x4.shared.b16 {%0,%1,%2,%3}, [%4];"
                 : "=r"(r[0]), "=r"(r[1]), "=r"(r[2]), "=r"(r[3]) : "r"(addr));
}
__device__ __forceinline__ void ldsm_x2(uint32_t* r, uint32_t addr) {
    asm volatile("ldmatrix.sync.aligned.m8n8.x2.shared.b16 {%0,%1}, [%2];"
                 : "=r"(r[0]), "=r"(r[1]) : "r"(addr));
}
__device__ __forceinline__ void mma_f16(float* d, const uint32_t* a, const uint32_t* b) {
    asm volatile("mma.sync.aligned.m16n8k16.row.col.f32.f16.f16.f32 "
                 "{%0,%1,%2,%3}, {%4,%5,%6,%7}, {%8,%9}, {%0,%1,%2,%3};"
                 : "+f"(d[0]), "+f"(d[1]), "+f"(d[2]), "+f"(d[3])
                 : "r"(a[0]), "r"(a[1]), "r"(a[2]), "r"(a[3]), "r"(b[0]), "r"(b[1]));
}

// =====================================================================
// Kernel B: gates GEMM + fused LSTM (bulk-copy pipeline, NKC=11).
// =====================================================================
#define SROW     40
#define XBYTES   10240
#define STAGE_SZ 20480
#define NSTAGE   5
#define MBAR_OFF (NSTAGE * STAGE_SZ)

__global__ void __launch_bounds__(256, 2)
gemm_lstm(const float* __restrict__ c,
          const float* __restrict__ b_ih, const float* __restrict__ b_hh)
{
    extern __shared__ char dyn[];
    __shared__ float sbias[128];
    const uint32_t uS = smem_u32(dyn);

    const int tid  = threadIdx.x;
    const int warp = tid >> 5, lane = tid & 31;
    const int n0  = blockIdx.y * 128;
    const int j0w = blockIdx.x * 128;
    const int j0g = blockIdx.x * 32;

    if (tid < 128) {
        int jg = j0g + (tid >> 2), gate = tid & 3;
        sbias[tid] = b_ih[gate * 256 + jg] + b_hh[gate * 256 + jg];
    }
    if (tid < NSTAGE) MBARRIER_INIT(uS + MBAR_OFF + tid * 8, 1);

    const int mw = (warp >> 2) * 64;
    const int nw = (warp & 3) * 32;

    float acc[4][4][4];
    #pragma unroll
    for (int a = 0; a < 4; ++a)
        #pragma unroll
        for (int b = 0; b < 4; ++b)
            #pragma unroll
            for (int r = 0; r < 4; ++r) acc[a][b][r] = 0.f;

    uint32_t aOff[4], bOff[4];
    {
        int arow = mw + ((lane >> 3) & 1) * 8 + (lane & 7);
        int acol = (lane >> 4) * 8;
        #pragma unroll
        for (int mf = 0; mf < 4; ++mf)
            aOff[mf] = ((arow + mf * 16) * SROW + acol) * 2;
        int brow = nw + (lane & 7);
        int bcol = ((lane >> 3) & 1) * 8;
        #pragma unroll
        for (int nf = 0; nf < 4; ++nf)
            bOff[nf] = ((brow + nf * 8) * SROW + bcol) * 2;
    }

    const __half* __restrict__ gX = g_X;
    const __half* __restrict__ gW = g_W;

    auto issue_stage = [&](int s, int kc) {
        uint32_t mb = uS + MBAR_OFF + s * 8;
        uint32_t sb = uS + (uint32_t)s * STAGE_SZ;
        MBARRIER_EXPECT_TX(mb, 2 * XBYTES);
        bulk_cp(sb,          gX + ((size_t)kc * NPED + n0)  * CROW, XBYTES, mb);
        bulk_cp(sb + XBYTES, gW + ((size_t)kc * 1024 + j0w) * CROW, XBYTES, mb);
    };

    __syncthreads();
    if (tid == 0) {
        issue_stage(0, 0);
        issue_stage(1, 1);
        issue_stage(2, 2);
        issue_stage(3, 3);
    }

    for (int kc = 0; kc < NKC; ++kc) {
        if (kc > 0) __syncthreads();
        if (tid == 0 && kc + 4 < NKC)
            issue_stage((kc + 4) % NSTAGE, kc + 4);
        MBAR_WAIT(uS + MBAR_OFF + (kc % NSTAGE) * 8, (uint32_t)((kc / NSTAGE) & 1));

        const uint32_t bufX = uS + (uint32_t)(kc % NSTAGE) * STAGE_SZ;
        const uint32_t bufW = bufX + XBYTES;
        #pragma unroll
        for (int ks = 0; ks < 2; ++ks) {
            uint32_t af[4][4], bf[4][2];
            #pragma unroll
            for (int mf = 0; mf < 4; ++mf)
                ldsm_x4(af[mf], bufX + aOff[mf] + ks * 32);
            #pragma unroll
            for (int nf = 0; nf < 4; ++nf)
                ldsm_x2(bf[nf], bufW + bOff[nf] + ks * 32);
            #pragma unroll
            for (int mf = 0; mf < 4; ++mf)
                #pragma unroll
                for (int nf = 0; nf < 4; ++nf)
                    mma_f16(acc[mf][nf], af[mf], bf[nf]);
        }
    }

    const int tig = lane & 3, g = lane >> 2;
    const bool even = !(tig & 1);
    #pragma unroll
    for (int mf = 0; mf < 4; ++mf) {
        #pragma unroll
        for (int nf = 0; nf < 4; ++nf) {
            float d0 = acc[mf][nf][0], d1 = acc[mf][nf][1];
            float d2 = acc[mf][nf][2], d3 = acc[mf][nf][3];
            float p0 = __shfl_xor_sync(0xffffffffu, d0, 1);
            float p1 = __shfl_xor_sync(0xffffffffu, d1, 1);
            float p2 = __shfl_xor_sync(0xffffffffu, d2, 1);
            float p3 = __shfl_xor_sync(0xffffffffu, d3, 1);
            int cl = nw + nf * 8 + 2 * tig;
            float gi, gf, gg, go;
            int rowl;
            if (even) {
                gi = d0 + sbias[cl];     gf = d1 + sbias[cl + 1];
                gg = p0 + sbias[cl + 2]; go = p1 + sbias[cl + 3];
                rowl = mw + mf * 16 + g;
            } else {
                gi = p2 + sbias[cl - 2]; gf = p3 + sbias[cl - 1];
                gg = d2 + sbias[cl];     go = d3 + sbias[cl + 1];
                rowl = mw + mf * 16 + g + 8;
            }
            int jj = (nw + nf * 8) / 4 + (tig >> 1);
            int n = n0 + rowl, j = j0g + jj;
            float cin = c[n * HID + j];
            float cn  = sigm(gf) * cin + sigm(gi) * tanh_f(gg);
            g_hnew[n * HID + j] = sigm(go) * tanh_f(cn);
        }
    }
}

// =====================================================================
// Kernel C: out = h_new @ W_pool^T + b_pool (R15 config, measured)
// =====================================================================
__global__ void __launch_bounds__(256) out_gemm(const float* __restrict__ W_pool,
                                                const float* __restrict__ b_pool,
                                                float* __restrict__ out)
{
    __shared__ float hs[16][68];
    __shared__ float ws[64][34];
    const int tid = threadIdx.x;
    const int n0 = blockIdx.x * 16;
    const int nl = tid >> 4, og = (tid & 15) * 2;

    float acc0 = 0.f, acc1 = 0.f;

    for (int kc = 0; kc < 4; ++kc) {
        {
            int r = tid >> 4, kq = tid & 15;
            float4 v = *(const float4*)&g_hnew[(n0 + r) * HID + kc * 64 + kq * 4];
            hs[r][kq * 4 + 0] = v.x; hs[r][kq * 4 + 1] = v.y;
            hs[r][kq * 4 + 2] = v.z; hs[r][kq * 4 + 3] = v.w;
        }
        #pragma unroll
        for (int it = 0; it < 2; ++it) {
            int l = tid + 256 * it;
            int o = l >> 4, kq = l & 15;
            float4 v = *(const float4*)&W_pool[o * HID + kc * 64 + kq * 4];
            ws[kq * 4 + 0][o] = v.x; ws[kq * 4 + 1][o] = v.y;
            ws[kq * 4 + 2][o] = v.z; ws[kq * 4 + 3][o] = v.w;
        }
        __syncthreads();
        #pragma unroll
        for (int k = 0; k < 64; k += 4) {
            float4 a = *(const float4*)&hs[nl][k];
            float2 w0 = *(const float2*)&ws[k + 0][og];
            float2 w1 = *(const float2*)&ws[k + 1][og];
            float2 w2 = *(const float2*)&ws[k + 2][og];
            float2 w3 = *(const float2*)&ws[k + 3][og];
            acc0 = fmaf(a.x, w0.x, acc0); acc1 = fmaf(a.x, w0.y, acc1);
            acc0 = fmaf(a.y, w1.x, acc0); acc1 = fmaf(a.y, w1.y, acc1);
            acc0 = fmaf(a.z, w2.x, acc0); acc1 = fmaf(a.z, w2.y, acc1);
            acc0 = fmaf(a.w, w3.x, acc0); acc1 = fmaf(a.w, w3.y, acc1);
        }
        __syncthreads();
    }
    float2 res;
    res.x = acc0 + b_pool[og];
    res.y = acc1 + b_pool[og + 1];
    *(float2*)&out[(n0 + nl) * OUTD + og] = res;
}

// =====================================================================
extern "C" void kernel_launch(void* const* d_in, const int* in_sizes, int n_in,
                              void* d_out, int out_size)
{
    (void)in_sizes; (void)n_in; (void)out_size;
    const float* obs1   = (const float*)d_in[0];
    const float* obs2   = (const float*)d_in[1];
    const float* h      = (const float*)d_in[2];
    const float* c      = (const float*)d_in[3];
    const float* W_emb  = (const float*)d_in[4];
    const float* b_emb  = (const float*)d_in[5];
    const float* W_ih   = (const float*)d_in[6];
    const float* b_ih   = (const float*)d_in[7];
    const float* W_hh   = (const float*)d_in[8];
    const float* b_hh   = (const float*)d_in[9];
    const float* W_pool = (const float*)d_in[10];
    const float* b_pool = (const float*)d_in[11];
    float* out = (float*)d_out;

    size_t smemA = (size_t)(2 * NPED) * 4
                 + (size_t)NPED * 4
                 + (size_t)(8 * 32 * 4) * 4 * 2
                 + 40 * 4
                 + (size_t)(32 * 32) * 2 * 2;
    size_t smemB = (size_t)MBAR_OFF + NSTAGE * 8 + 16;
    cudaFuncSetAttribute(knn_embed, cudaFuncAttributeMaxDynamicSharedMemorySize,
                         (int)smemA);
    cudaFuncSetAttribute(gemm_lstm, cudaFuncAttributeMaxDynamicSharedMemorySize,
                         (int)smemB);

    prep_xw  <<<(PX_TOT + PW_TOT + 255) / 256, 256>>>(h, W_ih, W_hh);
    knn_embed<<<NPED / 32, 256, smemA>>>(obs1, obs2, W_emb, b_emb);
    gemm_lstm<<<dim3(8, 48), 256, smemB>>>(c, b_ih, b_hh);
    out_gemm <<<NPED / 16, 256>>>(W_pool, b_pool, out);
}

// round 17
// speedup vs baseline: 1.2779x; 1.0453x over previous
#include <cuda_runtime.h>
#include <cuda_fp16.h>
#include <cstdint>

#define NPED 6144
#define HID  256
#define OUTD 32
#define NKC  11        // chunks: [hi 0..8 | emb_lo*Wih_hi 9 | emb_hi*Wih_lo 10]
#define CROW 40        // halves per row per chunk (32 data + 8 pad) = 80B

// ---------------- scratch (no allocation allowed) ----------------
__device__ float  g_hnew[NPED * HID];
__device__ __align__(16) __half g_X[NKC * NPED * CROW];
__device__ __align__(16) __half g_W[NKC * 1024 * CROW];

// ---------------- helpers ----------------
__device__ __forceinline__ uint32_t smem_u32(const void* p) {
    uint32_t a;
    asm("{ .reg .u64 t; cvta.to.shared.u64 t, %1; cvt.u32.u64 %0, t; }" : "=r"(a) : "l"(p));
    return a;
}
__device__ __forceinline__ void bulk_cp(uint32_t dst, const void* src,
                                        uint32_t bytes, uint32_t mbar) {
    asm volatile("cp.async.bulk.shared::cta.global.mbarrier::complete_tx::bytes "
                 "[%0], [%1], %2, [%3];"
                 :: "r"(dst), "l"(src), "r"(bytes), "r"(mbar) : "memory");
}
#define MBARRIER_INIT(a, c) \
    asm volatile("mbarrier.init.shared.b64 [%0], %1;" :: "r"(a), "r"(c) : "memory")
#define MBARRIER_EXPECT_TX(a, b) \
    asm volatile("mbarrier.arrive.expect_tx.shared.b64 _, [%0], %1;" \
                 :: "r"(a), "r"(b) : "memory")
#define MBAR_WAIT(a, p) do {                                                    \
    uint32_t _m = (a), _p = (p), _d;                                            \
    asm volatile("{\n\t.reg .pred q;\n\t"                                       \
        "mbarrier.try_wait.parity.acquire.cta.shared::cta.b64 q, [%1], %2;\n\t" \
        "selp.b32 %0, 1, 0, q;\n\t}" : "=r"(_d) : "r"(_m), "r"(_p) : "memory"); \
    if (!_d) {                                                                  \
        asm volatile("{\n\t.reg .pred Q;\n\tWL_%=:\n\t"                         \
        "mbarrier.try_wait.parity.acquire.cta.shared::cta.b64 Q, [%0], %1, 0x989680;\n\t" \
        "@Q bra.uni WD_%=;\n\tbra.uni WL_%=;\n\tWD_%=:\n\t}"                    \
        :: "r"(_m), "r"(_p) : "memory");                                        \
    } } while (0)

__device__ __forceinline__ bool dless(float d, int j, float dk, int ik) {
    return (d < dk) | ((d == dk) & (j < ik));
}
__device__ __forceinline__ float sigm(float x) { return 1.f / (1.f + __expf(-x)); }
__device__ __forceinline__ float tanh_f(float x) {
    float xx = fminf(fmaxf(x, -15.f), 15.f);
    float t  = __expf(-2.f * xx);
    return (1.f - t) / (1.f + t);
}
__device__ __forceinline__ ushort2 hilo(float x) {
    __half hb = __float2half_rn(x);
    __half lb = __float2half_rn(x - __half2float(hb));
    ushort2 r; r.x = __half_as_ushort(hb); r.y = __half_as_ushort(lb);
    return r;
}

// flattened lexicographic 4-best insert: single branch level, SEL body.
#define FLAT_INSERT(dd, jj)                                               \
    {                                                                     \
        bool lt3 = dless(dd, jj, d3v, i3v);                               \
        if (lt3) {                                                        \
            bool lt2 = dless(dd, jj, d2v, i2v);                           \
            bool lt1 = dless(dd, jj, d1v, i1v);                           \
            bool lt0 = dless(dd, jj, d0v, i0v);                           \
            float n3 = lt2 ? d2v : dd;  int m3 = lt2 ? i2v : jj;          \
            float n2 = lt2 ? (lt1 ? d1v : dd) : d2v;                      \
            int   m2 = lt2 ? (lt1 ? i1v : jj) : i2v;                      \
            float n1 = lt1 ? (lt0 ? d0v : dd) : d1v;                      \
            int   m1 = lt1 ? (lt0 ? i0v : jj) : i1v;                      \
            float n0 = lt0 ? dd : d0v;  int m0 = lt0 ? jj : i0v;          \
            d0v = n0; i0v = m0; d1v = n1; i1v = m1;                       \
            d2v = n2; i2v = m2; d3v = n3; i3v = m3;                       \
        }                                                                 \
    }

#define PX_TOT (NPED * 64)
#define PW_TOT (1024 * 76)
#define KNN_BLOCKS 192
#define PREP_BLOCKS 230           // (PX_TOT + PW_TOT) / 2048

// =====================================================================
// Kernel A: blocks [0,192) = 4-NN + embedding (R13/R16 measured scan);
// blocks [192, 422) = prep work (h-rows + W chunks), 8 elems/thread.
// =====================================================================
__global__ void __launch_bounds__(256) knn_prep(const float* __restrict__ obs1,
                                                const float* __restrict__ obs2,
                                                const float* __restrict__ h,
                                                const float* __restrict__ W_ih,
                                                const float* __restrict__ W_hh,
                                                const float* __restrict__ W_emb,
                                                const float* __restrict__ b_emb)
{
    const int tid = threadIdx.x;

    if (blockIdx.x >= KNN_BLOCKS) {
        // ---------------- prep path (former prep_xw) ----------------
        int pb = blockIdx.x - KNN_BLOCKS;
        #pragma unroll
        for (int it = 0; it < 8; ++it) {
            int idx = pb * 2048 + it * 256 + tid;
            if (idx < PX_TOT) {
                int row = idx >> 6, q = idx & 63;
                int s = q * 4;
                float4 v = *(const float4*)&h[row * 256 + s];
                __half h0 = __float2half_rn(v.x), h1 = __float2half_rn(v.y);
                __half h2 = __float2half_rn(v.z), h3 = __float2half_rn(v.w);
                ushort4 ph;
                ph.x = __half_as_ushort(h0); ph.y = __half_as_ushort(h1);
                ph.z = __half_as_ushort(h2); ph.w = __half_as_ushort(h3);
                int ch = 1 + (s >> 5), ci = s & 31;
                *(ushort4*)((ushort*)g_X + ((size_t)(ch * NPED + row)) * CROW + ci) = ph;
            } else if (idx < PX_TOT + PW_TOT) {
                int widx = idx - PX_TOT;
                int rowp = widx / 76, q = widx - rowp * 76;
                int j = rowp >> 2, gate = rowp & 3;
                int r = gate * 256 + j;
                if (q < 72) {
                    int s = q * 4;
                    float4 v = (s < 32) ? *(const float4*)&W_ih[r * 32 + s]
                                        : *(const float4*)&W_hh[r * 256 + (s - 32)];
                    ushort2 a = hilo(v.x), b = hilo(v.y), cc = hilo(v.z), d = hilo(v.w);
                    ushort4 ph;
                    ph.x = a.x; ph.y = b.x; ph.z = cc.x; ph.w = d.x;
                    int c0 = s >> 5, ci = s & 31;
                    *(ushort4*)((ushort*)g_W + ((size_t)(c0 * 1024 + rowp)) * CROW + ci) = ph;
                    if (c0 == 0)
                        *(ushort4*)((ushort*)g_W + ((size_t)(9 * 1024 + rowp)) * CROW + ci) = ph;
                } else {
                    int s2 = (q - 72) * 4;
                    float4 v = *(const float4*)&W_ih[r * 32 + s2];
                    ushort2 a = hilo(v.x), b = hilo(v.y), cc = hilo(v.z), d = hilo(v.w);
                    ushort4 pl;
                    pl.x = a.y; pl.y = b.y; pl.z = cc.y; pl.w = d.y;
                    *(ushort4*)((ushort*)g_W + ((size_t)(10 * 1024 + rowp)) * CROW + s2) = pl;
                }
            }
        }
        return;
    }

    // ---------------- knn path ----------------
    extern __shared__ float sm[];
    float2* sPos = (float2*)sm;
    float*  sHn  = sm + 2 * NPED;
    float*  sCd  = sHn + NPED;
    int*    sCi  = (int*)(sCd + 8 * 32 * 4);
    float*  sW   = (float*)(sCi + 8 * 32 * 4);
    ushort* sEh  = (ushort*)(sW + 40);
    ushort* sEl  = sEh + 32 * 32;

    const float2* o2 = (const float2*)obs2;
    const float2* o1 = (const float2*)obs1;
    for (int t = tid; t < NPED; t += 256) {
        float2 p = o2[t];
        sPos[t] = p;
        sHn[t]  = 0.5f * (p.x * p.x + p.y * p.y);
    }
    if (tid < 40) sW[tid] = (tid < 32) ? W_emb[tid] : b_emb[tid - 32];
    __syncthreads();

    const int li = tid & 31, part = tid >> 5;
    const int i = blockIdx.x * 32 + li;
    const float mx = sPos[i].x, my = sPos[i].y;
    const float nmx = -mx, nmy = -my;

    const float INF = __int_as_float(0x7f800000);
    float d0v = INF, d1v = INF, d2v = INF, d3v = INF;
    int   i0v = 0x7fffffff, i1v = 0x7fffffff, i2v = 0x7fffffff, i3v = 0x7fffffff;

    const float4* sP4 = (const float4*)sPos;
    const float4* sH4 = (const float4*)sHn;
    const int gbeg = part * 192, gend = gbeg + 192;
    const int gs = i >> 2;
    const int pSelf = blockIdx.x / 24;

#define GROUP_KEYS()                                                       \
    float4 pa = sP4[g * 2], pb = sP4[g * 2 + 1];                           \
    float4 hn = sH4[g];                                                    \
    float k0 = fmaf(nmx, pa.x, fmaf(nmy, pa.y, hn.x));                     \
    float k1 = fmaf(nmx, pa.z, fmaf(nmy, pa.w, hn.y));                     \
    float k2 = fmaf(nmx, pb.x, fmaf(nmy, pb.y, hn.z));                     \
    float k3 = fmaf(nmx, pb.z, fmaf(nmy, pb.w, hn.w));

#define GROUP_BODY()                                                       \
    float mn = fminf(fminf(k0, k1), fminf(k2, k3));                        \
    if (mn <= d3v) {                                                       \
        int jb = g * 4;                                                    \
        if (k0 <= d3v) { FLAT_INSERT(k0, jb + 0); }                        \
        if (k1 <= d3v) { FLAT_INSERT(k1, jb + 1); }                        \
        if (k2 <= d3v) { FLAT_INSERT(k2, jb + 2); }                        \
        if (k3 <= d3v) { FLAT_INSERT(k3, jb + 3); }                        \
    }

    if (part == pSelf) {
        for (int g = gbeg; g < gend; ++g) {
            GROUP_KEYS();
            if (g == gs) {
                int sl = i & 3;
                k0 = (sl == 0) ? INF : k0;
                k1 = (sl == 1) ? INF : k1;
                k2 = (sl == 2) ? INF : k2;
                k3 = (sl == 3) ? INF : k3;
            }
            GROUP_BODY();
        }
    } else {
        for (int g = gbeg; g < gend; ++g) {
            GROUP_KEYS();
            GROUP_BODY();
        }
    }
#undef GROUP_KEYS
#undef GROUP_BODY

    {
        int base = (part * 32 + li) * 4;
        sCd[base + 0] = d0v; sCi[base + 0] = i0v;
        sCd[base + 1] = d1v; sCi[base + 1] = i1v;
        sCd[base + 2] = d2v; sCi[base + 2] = i2v;
        sCd[base + 3] = d3v; sCi[base + 3] = i3v;
    }
    __syncthreads();

    if (part == 0) {
        d0v = d1v = d2v = d3v = INF;
        i0v = i1v = i2v = i3v = 0x7fffffff;
        #pragma unroll
        for (int p = 0; p < 8; ++p)
            #pragma unroll
            for (int s = 0; s < 4; ++s) {
                float dd = sCd[(p * 32 + li) * 4 + s];
                int   jj = sCi[(p * 32 + li) * 4 + s];
                FLAT_INSERT(dd, jj);
            }

        float2 o1i = o1[i];
        const float vix = mx - o1i.x, viy = my - o1i.y;
        int nb[4] = {i0v, i1v, i2v, i3v};
        #pragma unroll
        for (int k = 0; k < 4; ++k) {
            float2 np = sPos[nb[k]];
            float2 o1n = o1[nb[k]];
            float px = np.x - mx, py = np.y - my;
            float vx = (np.x - o1n.x) - vix, vy = (np.y - o1n.y) - viy;
            #pragma unroll
            for (int e = 0; e < 8; ++e) {
                float v = sW[32 + e] + px * sW[e] + py * sW[8 + e]
                        + vx * sW[16 + e] + vy * sW[24 + e];
                v = fmaxf(v, 0.f);
                ushort2 hl = hilo(v);
                sEh[li * 32 + k * 8 + e] = hl.x;
                sEl[li * 32 + k * 8 + e] = hl.y;
            }
        }
    }
    __syncthreads();

    // emb -> g_X chunks: hi -> chunk 0, lo -> chunk 9, hi -> chunk 10
    {
        int r = tid >> 3, q = tid & 7;
        int gr = blockIdx.x * 32 + r;
        ushort4 vh = *(const ushort4*)&sEh[r * 32 + q * 4];
        ushort4 vl = *(const ushort4*)&sEl[r * 32 + q * 4];
        *(ushort4*)((ushort*)g_X + ((size_t)(0 * NPED + gr)) * CROW + q * 4)  = vh;
        *(ushort4*)((ushort*)g_X + ((size_t)(9 * NPED + gr)) * CROW + q * 4)  = vl;
        *(ushort4*)((ushort*)g_X + ((size_t)(10 * NPED + gr)) * CROW + q * 4) = vh;
    }
}

// ---------------- mma/ldmatrix wrappers ----------------
__device__ __forceinline__ void ldsm_x4(uint32_t* r, uint32_t addr) {
    asm volatile("ldmatrix.sync.aligned.m8n8.x4.shared.b16 {%0,%1,%2,%3}, [%4];"
                 : "=r"(r[0]), "=r"(r[1]), "=r"(r[2]), "=r"(r[3]) : "r"(addr));
}
__device__ __forceinline__ void ldsm_x2(uint32_t* r, uint32_t addr) {
    asm volatile("ldmatrix.sync.aligned.m8n8.x2.shared.b16 {%0,%1}, [%2];"
                 : "=r"(r[0]), "=r"(r[1]) : "r"(addr));
}
__device__ __forceinline__ void mma_f16(float* d, const uint32_t* a, const uint32_t* b) {
    asm volatile("mma.sync.aligned.m16n8k16.row.col.f32.f16.f16.f32 "
                 "{%0,%1,%2,%3}, {%4,%5,%6,%7}, {%8,%9}, {%0,%1,%2,%3};"
                 : "+f"(d[0]), "+f"(d[1]), "+f"(d[2]), "+f"(d[3])
                 : "r"(a[0]), "r"(a[1]), "r"(a[2]), "r"(a[3]), "r"(b[0]), "r"(b[1]));
}

// =====================================================================
// Kernel B: gates GEMM + fused LSTM (R16 config, NKC=11).
// =====================================================================
#define SROW     40
#define XBYTES   10240
#define STAGE_SZ 20480
#define NSTAGE   5
#define MBAR_OFF (NSTAGE * STAGE_SZ)

__global__ void __launch_bounds__(256, 2)
gemm_lstm(const float* __restrict__ c,
          const float* __restrict__ b_ih, const float* __restrict__ b_hh)
{
    extern __shared__ char dyn[];
    __shared__ float sbias[128];
    const uint32_t uS = smem_u32(dyn);

    const int tid  = threadIdx.x;
    const int warp = tid >> 5, lane = tid & 31;
    const int n0  = blockIdx.y * 128;
    const int j0w = blockIdx.x * 128;
    const int j0g = blockIdx.x * 32;

    if (tid < 128) {
        int jg = j0g + (tid >> 2), gate = tid & 3;
        sbias[tid] = b_ih[gate * 256 + jg] + b_hh[gate * 256 + jg];
    }
    if (tid < NSTAGE) MBARRIER_INIT(uS + MBAR_OFF + tid * 8, 1);

    const int mw = (warp >> 2) * 64;
    const int nw = (warp & 3) * 32;

    float acc[4][4][4];
    #pragma unroll
    for (int a = 0; a < 4; ++a)
        #pragma unroll
        for (int b = 0; b < 4; ++b)
            #pragma unroll
            for (int r = 0; r < 4; ++r) acc[a][b][r] = 0.f;

    uint32_t aOff[4], bOff[4];
    {
        int arow = mw + ((lane >> 3) & 1) * 8 + (lane & 7);
        int acol = (lane >> 4) * 8;
        #pragma unroll
        for (int mf = 0; mf < 4; ++mf)
            aOff[mf] = ((arow + mf * 16) * SROW + acol) * 2;
        int brow = nw + (lane & 7);
        int bcol = ((lane >> 3) & 1) * 8;
        #pragma unroll
        for (int nf = 0; nf < 4; ++nf)
            bOff[nf] = ((brow + nf * 8) * SROW + bcol) * 2;
    }

    const __half* __restrict__ gX = g_X;
    const __half* __restrict__ gW = g_W;

    auto issue_stage = [&](int s, int kc) {
        uint32_t mb = uS + MBAR_OFF + s * 8;
        uint32_t sb = uS + (uint32_t)s * STAGE_SZ;
        MBARRIER_EXPECT_TX(mb, 2 * XBYTES);
        bulk_cp(sb,          gX + ((size_t)kc * NPED + n0)  * CROW, XBYTES, mb);
        bulk_cp(sb + XBYTES, gW + ((size_t)kc * 1024 + j0w) * CROW, XBYTES, mb);
    };

    __syncthreads();
    if (tid == 0) {
        issue_stage(0, 0);
        issue_stage(1, 1);
        issue_stage(2, 2);
        issue_stage(3, 3);
    }

    for (int kc = 0; kc < NKC; ++kc) {
        if (kc > 0) __syncthreads();
        if (tid == 0 && kc + 4 < NKC)
            issue_stage((kc + 4) % NSTAGE, kc + 4);
        MBAR_WAIT(uS + MBAR_OFF + (kc % NSTAGE) * 8, (uint32_t)((kc / NSTAGE) & 1));

        const uint32_t bufX = uS + (uint32_t)(kc % NSTAGE) * STAGE_SZ;
        const uint32_t bufW = bufX + XBYTES;
        #pragma unroll
        for (int ks = 0; ks < 2; ++ks) {
            uint32_t af[4][4], bf[4][2];
            #pragma unroll
            for (int mf = 0; mf < 4; ++mf)
                ldsm_x4(af[mf], bufX + aOff[mf] + ks * 32);
            #pragma unroll
            for (int nf = 0; nf < 4; ++nf)
                ldsm_x2(bf[nf], bufW + bOff[nf] + ks * 32);
            #pragma unroll
            for (int mf = 0; mf < 4; ++mf)
                #pragma unroll
                for (int nf = 0; nf < 4; ++nf)
                    mma_f16(acc[mf][nf], af[mf], bf[nf]);
        }
    }

    const int tig = lane & 3, g = lane >> 2;
    const bool even = !(tig & 1);
    #pragma unroll
    for (int mf = 0; mf < 4; ++mf) {
        #pragma unroll
        for (int nf = 0; nf < 4; ++nf) {
            float d0 = acc[mf][nf][0], d1 = acc[mf][nf][1];
            float d2 = acc[mf][nf][2], d3 = acc[mf][nf][3];
            float p0 = __shfl_xor_sync(0xffffffffu, d0, 1);
            float p1 = __shfl_xor_sync(0xffffffffu, d1, 1);
            float p2 = __shfl_xor_sync(0xffffffffu, d2, 1);
            float p3 = __shfl_xor_sync(0xffffffffu, d3, 1);
            int cl = nw + nf * 8 + 2 * tig;
            float gi, gf, gg, go;
            int rowl;
            if (even) {
                gi = d0 + sbias[cl];     gf = d1 + sbias[cl + 1];
                gg = p0 + sbias[cl + 2]; go = p1 + sbias[cl + 3];
                rowl = mw + mf * 16 + g;
            } else {
                gi = p2 + sbias[cl - 2]; gf = p3 + sbias[cl - 1];
                gg = d2 + sbias[cl];     go = d3 + sbias[cl + 1];
                rowl = mw + mf * 16 + g + 8;
            }
            int jj = (nw + nf * 8) / 4 + (tig >> 1);
            int n = n0 + rowl, j = j0g + jj;
            float cin = c[n * HID + j];
            float cn  = sigm(gf) * cin + sigm(gi) * tanh_f(gg);
            g_hnew[n * HID + j] = sigm(go) * tanh_f(cn);
        }
    }
}

// =====================================================================
// Kernel C: out = h_new @ W_pool^T + b_pool.
// 192 blocks x 128 threads; warp = 8 rows, lane = 1 output col.
// Per 4-k: 4 scalar w-LDS (conflict-free) + 8 broadcast h-LDS.128
// -> 12 LDS / 32 FMA (vs 5/8 before).
// =====================================================================
__global__ void __launch_bounds__(128) out_gemm(const float* __restrict__ W_pool,
                                                const float* __restrict__ b_pool,
                                                float* __restrict__ out)
{
    __shared__ float hs[32][68];
    __shared__ float ws[64][33];
    const int tid = threadIdx.x;
    const int warp = tid >> 5, lane = tid & 31;
    const int n0 = blockIdx.x * 32;
    const int r0 = warp * 8;

    float acc[8];
    #pragma unroll
    for (int u = 0; u < 8; ++u) acc[u] = 0.f;

    for (int kc = 0; kc < 4; ++kc) {
        #pragma unroll
        for (int it = 0; it < 4; ++it) {   // hs: 32 rows x 64 k
            int idx = tid + 128 * it;
            int r = idx >> 4, kq = idx & 15;
            float4 v = *(const float4*)&g_hnew[(n0 + r) * HID + kc * 64 + kq * 4];
            hs[r][kq * 4 + 0] = v.x; hs[r][kq * 4 + 1] = v.y;
            hs[r][kq * 4 + 2] = v.z; hs[r][kq * 4 + 3] = v.w;
        }
        #pragma unroll
        for (int it = 0; it < 4; ++it) {   // ws: 32 cols x 64 k
            int idx = tid + 128 * it;
            int o = idx >> 4, kq = idx & 15;
            float4 v = *(const float4*)&W_pool[o * HID + kc * 64 + kq * 4];
            ws[kq * 4 + 0][o] = v.x; ws[kq * 4 + 1][o] = v.y;
            ws[kq * 4 + 2][o] = v.z; ws[kq * 4 + 3][o] = v.w;
        }
        __syncthreads();
        #pragma unroll
        for (int k = 0; k < 64; k += 4) {
            float w0 = ws[k + 0][lane];
            float w1 = ws[k + 1][lane];
            float w2 = ws[k + 2][lane];
            float w3 = ws[k + 3][lane];
            #pragma unroll
            for (int u = 0; u < 8; ++u) {
                float4 a = *(const float4*)&hs[r0 + u][k];
                acc[u] = fmaf(a.x, w0, acc[u]);
                acc[u] = fmaf(a.y, w1, acc[u]);
                acc[u] = fmaf(a.z, w2, acc[u]);
                acc[u] = fmaf(a.w, w3, acc[u]);
            }
        }
        __syncthreads();
    }
    float bp = b_pool[lane];
    #pragma unroll
    for (int u = 0; u < 8; ++u)
        out[(n0 + r0 + u) * OUTD + lane] = acc[u] + bp;
}

// =====================================================================
extern "C" void kernel_launch(void* const* d_in, const int* in_sizes, int n_in,
                              void* d_out, int out_size)
{
    (void)in_sizes; (void)n_in; (void)out_size;
    const float* obs1   = (const float*)d_in[0];
    const float* obs2   = (const float*)d_in[1];
    const float* h      = (const float*)d_in[2];
    const float* c      = (const float*)d_in[3];
    const float* W_emb  = (const float*)d_in[4];
    const float* b_emb  = (const float*)d_in[5];
    const float* W_ih   = (const float*)d_in[6];
    const float* b_ih   = (const float*)d_in[7];
    const float* W_hh   = (const float*)d_in[8];
    const float* b_hh   = (const float*)d_in[9];
    const float* W_pool = (const float*)d_in[10];
    const float* b_pool = (const float*)d_in[11];
    float* out = (float*)d_out;

    size_t smemA = (size_t)(2 * NPED) * 4
                 + (size_t)NPED * 4
                 + (size_t)(8 * 32 * 4) * 4 * 2
                 + 40 * 4
                 + (size_t)(32 * 32) * 2 * 2;
    size_t smemB = (size_t)MBAR_OFF + NSTAGE * 8 + 16;
    cudaFuncSetAttribute(knn_prep, cudaFuncAttributeMaxDynamicSharedMemorySize,
                         (int)smemA);
    cudaFuncSetAttribute(gemm_lstm, cudaFuncAttributeMaxDynamicSharedMemorySize,
                         (int)smemB);

    knn_prep <<<KNN_BLOCKS + PREP_BLOCKS, 256, smemA>>>(obs1, obs2, h, W_ih, W_hh,
                                                        W_emb, b_emb);
    gemm_lstm<<<dim3(8, 48), 256, smemB>>>(c, b_ih, b_hh);
    out_gemm <<<NPED / 32, 128>>>(W_pool, b_pool, out);
}